// round 3
// baseline (speedup 1.0000x reference)
#include <cuda_runtime.h>
#include <cuda_bf16.h>
#include <cstdint>

typedef unsigned long long u64;

#define B_DIM 4096
#define T_DIM 1024
#define VOCAB 32000
#define HID 16

// ---------------- scratch (no allocations allowed) ----------------
__device__ float g_P[VOCAB * HID];          // projected embedding table: Wx@e + b   (2 MB)
__device__ u64   g_Wt2[(VOCAB / 2) * HID];  // out_w packed per v-pair: (w[2p][k], w[2p+1][k]) (2 MB)
__device__ float g_H[B_DIM * HID];          // final hidden states (256 KB)

// ---------------- f32x2 helpers ----------------
__device__ __forceinline__ u64 pack2(float x, float y) {
    u64 r; asm("mov.b64 %0, {%1, %2};" : "=l"(r) : "f"(x), "f"(y)); return r;
}
__device__ __forceinline__ float2 unpack2(u64 v) {
    float2 f; asm("mov.b64 {%0, %1}, %2;" : "=f"(f.x), "=f"(f.y) : "l"(v)); return f;
}
__device__ __forceinline__ u64 ffma2(u64 a, u64 b, u64 c) {
    u64 d; asm("fma.rn.f32x2 %0, %1, %2, %3;" : "=l"(d) : "l"(a), "l"(b), "l"(c)); return d;
}

// ---------------- kernel 0: precompute P and packed out_w ----------------
__global__ __launch_bounds__(256) void prep_kernel(
    const float* __restrict__ embed, const float* __restrict__ Wx_w,
    const float* __restrict__ Wx_b, const float* __restrict__ out_w)
{
    int idx = blockIdx.x * blockDim.x + threadIdx.x;
    if (idx < VOCAB * HID) {
        int v = idx >> 4, i = idx & 15;
        float acc = Wx_b[i];
        #pragma unroll
        for (int j = 0; j < 16; j++)
            acc = fmaf(embed[v * 16 + j], Wx_w[i * 16 + j], acc);
        g_P[idx] = acc;
    }
    int idx2 = idx - VOCAB * HID;
    if (idx2 >= 0 && idx2 < (VOCAB / 2) * HID) {
        int vp = idx2 >> 4, k = idx2 & 15;
        g_Wt2[idx2] = pack2(out_w[(2 * vp) * 16 + k], out_w[(2 * vp + 1) * 16 + k]);
    }
}

// ---------------- kernel 1: the sequential recurrence ----------------
// thread = (row, i): 16 lanes per row, 2 rows per warp. h[i] in a register,
// all-to-all via shfl width 16. Tokens loaded int4 (4 steps), P gathers
// software-pipelined one 4-step block ahead to hide L2 latency.

__device__ __forceinline__ float tanh_fast(float z) {
    // 1 - 2/(exp(2z)+1); exact at +-inf, abs err ~1e-7
    float e = __expf(2.0f * z);
    return 1.0f - __fdividef(2.0f, e + 1.0f);
}

__device__ __forceinline__ float rstep(float h, float xp, const float* w) {
    float a0 = xp, a1 = 0.f, a2 = 0.f, a3 = 0.f;
    #pragma unroll
    for (int j = 0; j < 16; j += 4) {
        float h0 = __shfl_sync(0xffffffffu, h, j,     16);
        float h1 = __shfl_sync(0xffffffffu, h, j + 1, 16);
        float h2 = __shfl_sync(0xffffffffu, h, j + 2, 16);
        float h3 = __shfl_sync(0xffffffffu, h, j + 3, 16);
        a0 = fmaf(w[j],     h0, a0);
        a1 = fmaf(w[j + 1], h1, a1);
        a2 = fmaf(w[j + 2], h2, a2);
        a3 = fmaf(w[j + 3], h3, a3);
    }
    return tanh_fast((a0 + a1) + (a2 + a3));
}

__global__ __launch_bounds__(256) void rnn_kernel(
    const int* __restrict__ seq, const float* __restrict__ Wh)
{
    int gid = blockIdx.x * blockDim.x + threadIdx.x;
    int r = gid >> 4;
    int i = gid & 15;

    float w[16];
    #pragma unroll
    for (int j = 0; j < 16; j++) w[j] = __ldg(Wh + i * 16 + j);

    const int* sr = seq + (size_t)r * T_DIM;
    const float* P = g_P;

    float h = 0.0f;
    int4 tk = *(const int4*)sr;
    float xp0 = __ldg(P + tk.x * 16 + i);
    float xp1 = __ldg(P + tk.y * 16 + i);
    float xp2 = __ldg(P + tk.z * 16 + i);
    float xp3 = __ldg(P + tk.w * 16 + i);

    for (int t = 0; t < T_DIM; t += 4) {
        int tn = (t + 4 < T_DIM) ? (t + 4) : 0;   // clamp: last prefetch harmless
        int4 tkn = *(const int4*)(sr + tn);

        h = rstep(h, xp0, w);
        h = rstep(h, xp1, w);

        float n0 = __ldg(P + tkn.x * 16 + i);
        float n1 = __ldg(P + tkn.y * 16 + i);
        float n2 = __ldg(P + tkn.z * 16 + i);
        float n3 = __ldg(P + tkn.w * 16 + i);

        h = rstep(h, xp2, w);
        h = rstep(h, xp3, w);

        xp0 = n0; xp1 = n1; xp2 = n2; xp3 = n3;
    }
    g_H[gid] = h;
}

// ---------------- kernel 2: out = H @ out_w^T + out_b via f32x2 ----------------
// Block tile: 128 rows x 1024 cols. Thread: 4 consecutive v (2 packed v-pairs,
// weights in 64 regs), loops the 128 rows; h broadcast-packed (h,h) in smem.
// out_w L2 traffic = 32 row-blocks * 2MB = 64MB.

__global__ __launch_bounds__(256) void gemm_kernel(
    const float* __restrict__ bias, float* __restrict__ out)
{
    __shared__ u64 hs[128 * 16];   // (h,h) packed, 16 KB

    int rb = blockIdx.y * 128;
    int vb = blockIdx.x * 1024;

    for (int idx = threadIdx.x; idx < 128 * 16; idx += 256) {
        float v = g_H[rb * 16 + idx];
        hs[idx] = pack2(v, v);
    }
    __syncthreads();

    int v0 = vb + threadIdx.x * 4;
    if (v0 >= VOCAB) return;

    int vp0 = v0 >> 1;
    u64 w2a[16], w2b[16];
    #pragma unroll
    for (int k = 0; k < 16; k++) {
        w2a[k] = __ldg(g_Wt2 + (size_t)vp0 * 16 + k);
        w2b[k] = __ldg(g_Wt2 + (size_t)(vp0 + 1) * 16 + k);
    }
    u64 ba = *(const u64*)(bias + v0);       // (b[v0], b[v0+1]) — 8B aligned (v0 % 4 == 0)
    u64 bb = *(const u64*)(bias + v0 + 2);

    for (int r = 0; r < 128; r++) {
        const ulonglong2* hp = (const ulonglong2*)(hs + r * 16);
        u64 aA = ba, aB = bb;
        #pragma unroll
        for (int k = 0; k < 16; k += 2) {
            ulonglong2 hh = hp[k >> 1];
            aA = ffma2(hh.x, w2a[k],     aA);
            aB = ffma2(hh.x, w2b[k],     aB);
            aA = ffma2(hh.y, w2a[k + 1], aA);
            aB = ffma2(hh.y, w2b[k + 1], aB);
        }
        float2 fa = unpack2(aA);
        float2 fb = unpack2(aB);
        float4 o = make_float4(fa.x, fa.y, fb.x, fb.y);
        *(float4*)(out + (size_t)(rb + r) * VOCAB + v0) = o;
    }
}

// ---------------- launch ----------------
extern "C" void kernel_launch(void* const* d_in, const int* in_sizes, int n_in,
                              void* d_out, int out_size)
{
    const int*   seq   = (const int*)d_in[0];
    const float* embed = (const float*)d_in[1];
    const float* Wh    = (const float*)d_in[2];
    const float* Wx_w  = (const float*)d_in[3];
    const float* Wx_b  = (const float*)d_in[4];
    const float* out_w = (const float*)d_in[5];
    const float* out_b = (const float*)d_in[6];
    float* out = (float*)d_out;

    int prep_items = VOCAB * HID + (VOCAB / 2) * HID;   // 768000
    prep_kernel<<<(prep_items + 255) / 256, 256>>>(embed, Wx_w, Wx_b, out_w);

    rnn_kernel<<<(B_DIM * HID) / 256, 256>>>(seq, Wh);

    dim3 ggrid((VOCAB + 1023) / 1024, B_DIM / 128);     // (32, 32)
    gemm_kernel<<<ggrid, 256>>>(out_b, out);
}

// round 4
// speedup vs baseline: 1.2176x; 1.2176x over previous
#include <cuda_runtime.h>
#include <cuda_bf16.h>
#include <cstdint>

typedef unsigned long long u64;

#define B_DIM 4096
#define T_DIM 1024
#define VOCAB 32000
#define HID 16

// ---------------- scratch (no allocations allowed) ----------------
__device__ float g_P[VOCAB * HID];   // projected embedding table: Wx@e + b (2 MB)
__device__ float g_H[B_DIM * HID];   // final hidden states (256 KB)

// ---------------- f32x2 helpers ----------------
__device__ __forceinline__ u64 pack2(float x, float y) {
    u64 r; asm("mov.b64 %0, {%1, %2};" : "=l"(r) : "f"(x), "f"(y)); return r;
}
__device__ __forceinline__ float2 unpack2(u64 v) {
    float2 f; asm("mov.b64 {%0, %1}, %2;" : "=f"(f.x), "=f"(f.y) : "l"(v)); return f;
}
__device__ __forceinline__ u64 ffma2(u64 a, u64 b, u64 c) {
    u64 d; asm("fma.rn.f32x2 %0, %1, %2, %3;" : "=l"(d) : "l"(a), "l"(b), "l"(c)); return d;
}

// ---------------- kernel 0: P = embed @ Wx^T + b ----------------
// Block = 256 threads = 16 vocab rows x 16 dims. Embed rows staged in smem
// once (float4), Wx broadcast-hot in L1.
__global__ __launch_bounds__(256) void prep_kernel(
    const float* __restrict__ embed, const float* __restrict__ Wx_w,
    const float* __restrict__ Wx_b)
{
    __shared__ float e[16][16];
    int t = threadIdx.x;
    int v0 = blockIdx.x * 16;

    if (t < 64) {
        int vv = t >> 2, c = t & 3;
        ((float4*)e[vv])[c] = __ldg((const float4*)(embed + (size_t)(v0 + vv) * 16) + c);
    }
    __syncthreads();

    int vl = t >> 4, i = t & 15;
    const float4* er = (const float4*)e[vl];
    float4 e0 = er[0], e1 = er[1], e2 = er[2], e3 = er[3];
    const float* wr = Wx_w + i * 16;

    float a0 = __ldg(Wx_b + i), a1 = 0.f, a2 = 0.f, a3 = 0.f;
    a0 = fmaf(__ldg(wr + 0),  e0.x, a0);  a1 = fmaf(__ldg(wr + 1),  e0.y, a1);
    a2 = fmaf(__ldg(wr + 2),  e0.z, a2);  a3 = fmaf(__ldg(wr + 3),  e0.w, a3);
    a0 = fmaf(__ldg(wr + 4),  e1.x, a0);  a1 = fmaf(__ldg(wr + 5),  e1.y, a1);
    a2 = fmaf(__ldg(wr + 6),  e1.z, a2);  a3 = fmaf(__ldg(wr + 7),  e1.w, a3);
    a0 = fmaf(__ldg(wr + 8),  e2.x, a0);  a1 = fmaf(__ldg(wr + 9),  e2.y, a1);
    a2 = fmaf(__ldg(wr + 10), e2.z, a2);  a3 = fmaf(__ldg(wr + 11), e2.w, a3);
    a0 = fmaf(__ldg(wr + 12), e3.x, a0);  a1 = fmaf(__ldg(wr + 13), e3.y, a1);
    a2 = fmaf(__ldg(wr + 14), e3.z, a2);  a3 = fmaf(__ldg(wr + 15), e3.w, a3);

    g_P[(size_t)(v0 + vl) * 16 + i] = (a0 + a1) + (a2 + a3);
}

// ---------------- kernel 1: the sequential recurrence ----------------
// NO shuffles. Lane (row, i) keeps h[i]; exchange via double-buffered smem:
// 1 STS.32 per row + 1 __syncwarp per step, read back as 4 broadcast LDS.128.
// Each thread drives TWO rows (rA, rB = rA+2) to interleave dependency chains.
// Warp covers 4 rows; block = 256 threads = 32 rows; grid = 128 blocks.

__device__ __forceinline__ float tanh_fast(float z) {
    float e = __expf(2.0f * z);
    return 1.0f - __fdividef(2.0f, e + 1.0f);
}

__device__ __forceinline__ float stepdot(const float* __restrict__ w,
                                         const float4* __restrict__ hrow, float xp) {
    float4 h0 = hrow[0], h1 = hrow[1], h2 = hrow[2], h3 = hrow[3];
    float a0 = xp, a1 = 0.f, a2 = 0.f, a3 = 0.f;
    a0 = fmaf(w[0],  h0.x, a0);  a1 = fmaf(w[1],  h0.y, a1);
    a2 = fmaf(w[2],  h0.z, a2);  a3 = fmaf(w[3],  h0.w, a3);
    a0 = fmaf(w[4],  h1.x, a0);  a1 = fmaf(w[5],  h1.y, a1);
    a2 = fmaf(w[6],  h1.z, a2);  a3 = fmaf(w[7],  h1.w, a3);
    a0 = fmaf(w[8],  h2.x, a0);  a1 = fmaf(w[9],  h2.y, a1);
    a2 = fmaf(w[10], h2.z, a2);  a3 = fmaf(w[11], h2.w, a3);
    a0 = fmaf(w[12], h3.x, a0);  a1 = fmaf(w[13], h3.y, a1);
    a2 = fmaf(w[14], h3.z, a2);  a3 = fmaf(w[15], h3.w, a3);
    return tanh_fast((a0 + a1) + (a2 + a3));
}

__global__ __launch_bounds__(256) void rnn_kernel(
    const int* __restrict__ seq, const float* __restrict__ Wh)
{
    __shared__ float hbuf[2][32][16];

    int t = threadIdx.x;
    int warp = t >> 5, lane = t & 31;
    int i = lane & 15, rs = lane >> 4;
    int rA = warp * 4 + rs;          // block-local rows
    int rB = rA + 2;
    int gA = blockIdx.x * 32 + rA;   // global rows
    int gB = blockIdx.x * 32 + rB;

    float w[16];
    #pragma unroll
    for (int j = 0; j < 16; j++) w[j] = __ldg(Wh + i * 16 + j);

    const int* sA = seq + (size_t)gA * T_DIM;
    const int* sB = seq + (size_t)gB * T_DIM;
    const float* P = g_P;

    hbuf[0][rA][i] = 0.0f;
    hbuf[0][rB][i] = 0.0f;
    __syncwarp();

    // 4-step lookahead on the P gathers
    int4 tkA = *(const int4*)sA;
    int4 tkB = *(const int4*)sB;
    float xA0 = __ldg(P + (size_t)tkA.x * 16 + i);
    float xA1 = __ldg(P + (size_t)tkA.y * 16 + i);
    float xA2 = __ldg(P + (size_t)tkA.z * 16 + i);
    float xA3 = __ldg(P + (size_t)tkA.w * 16 + i);
    float xB0 = __ldg(P + (size_t)tkB.x * 16 + i);
    float xB1 = __ldg(P + (size_t)tkB.y * 16 + i);
    float xB2 = __ldg(P + (size_t)tkB.z * 16 + i);
    float xB3 = __ldg(P + (size_t)tkB.w * 16 + i);

    #define RSTEP(SRC, DST, XA, XB)                                          \
        {                                                                    \
            float nA = stepdot(w, (const float4*)hbuf[SRC][rA], XA);         \
            float nB = stepdot(w, (const float4*)hbuf[SRC][rB], XB);         \
            hbuf[DST][rA][i] = nA;                                           \
            hbuf[DST][rB][i] = nB;                                           \
            __syncwarp();                                                    \
        }

    for (int tt = 0; tt < T_DIM; tt += 4) {
        int tn = (tt + 4 < T_DIM) ? (tt + 4) : 0;   // clamped last prefetch (unused)
        int4 nA4 = *(const int4*)(sA + tn);
        int4 nB4 = *(const int4*)(sB + tn);

        RSTEP(0, 1, xA0, xB0)
        RSTEP(1, 0, xA1, xB1)

        float pA0 = __ldg(P + (size_t)nA4.x * 16 + i);
        float pA1 = __ldg(P + (size_t)nA4.y * 16 + i);
        float pA2 = __ldg(P + (size_t)nA4.z * 16 + i);
        float pA3 = __ldg(P + (size_t)nA4.w * 16 + i);
        float pB0 = __ldg(P + (size_t)nB4.x * 16 + i);
        float pB1 = __ldg(P + (size_t)nB4.y * 16 + i);
        float pB2 = __ldg(P + (size_t)nB4.z * 16 + i);
        float pB3 = __ldg(P + (size_t)nB4.w * 16 + i);

        RSTEP(0, 1, xA2, xB2)
        RSTEP(1, 0, xA3, xB3)

        xA0 = pA0; xA1 = pA1; xA2 = pA2; xA3 = pA3;
        xB0 = pB0; xB1 = pB1; xB2 = pB2; xB3 = pB3;
    }
    #undef RSTEP

    // T_DIM multiple of 4 -> final state sits in buffer 0; own lane wrote it.
    g_H[(size_t)gA * 16 + i] = hbuf[0][rA][i];
    g_H[(size_t)gB * 16 + i] = hbuf[0][rB][i];
}

// ---------------- kernel 2: out = H @ out_w^T + out_b via f32x2 ----------------
// Block tile: 128 rows x 1024 cols. Thread: 4 consecutive v, out_w loaded
// directly (float4) and packed to f32x2 in-register; h broadcast-packed in smem.

__global__ __launch_bounds__(256) void gemm_kernel(
    const float* __restrict__ out_w, const float* __restrict__ bias,
    float* __restrict__ out)
{
    __shared__ u64 hs[128 * 16];   // (h,h) packed, 16 KB

    int rb = blockIdx.y * 128;
    int vb = blockIdx.x * 1024;

    for (int idx = threadIdx.x; idx < 128 * 16; idx += 256) {
        float v = g_H[(size_t)rb * 16 + idx];
        hs[idx] = pack2(v, v);
    }
    __syncthreads();

    int v0 = vb + threadIdx.x * 4;
    if (v0 >= VOCAB) return;

    // Load 4 weight rows and pack per v-pair: w2a[k]=(w[v0][k],w[v0+1][k])
    float wv[4][16];
    #pragma unroll
    for (int r = 0; r < 4; r++) {
        const float4* wr = (const float4*)(out_w + (size_t)(v0 + r) * 16);
        #pragma unroll
        for (int c = 0; c < 4; c++)
            ((float4*)wv[r])[c] = __ldg(wr + c);
    }
    u64 w2a[16], w2b[16];
    #pragma unroll
    for (int k = 0; k < 16; k++) {
        w2a[k] = pack2(wv[0][k], wv[1][k]);
        w2b[k] = pack2(wv[2][k], wv[3][k]);
    }
    u64 ba = *(const u64*)(bias + v0);
    u64 bb = *(const u64*)(bias + v0 + 2);

    for (int r = 0; r < 128; r++) {
        const ulonglong2* hp = (const ulonglong2*)(hs + r * 16);
        u64 aA = ba, aB = bb;
        #pragma unroll
        for (int k = 0; k < 16; k += 2) {
            ulonglong2 hh = hp[k >> 1];
            aA = ffma2(hh.x, w2a[k],     aA);
            aB = ffma2(hh.x, w2b[k],     aB);
            aA = ffma2(hh.y, w2a[k + 1], aA);
            aB = ffma2(hh.y, w2b[k + 1], aB);
        }
        float2 fa = unpack2(aA);
        float2 fb = unpack2(aB);
        *(float4*)(out + (size_t)(rb + r) * VOCAB + v0) =
            make_float4(fa.x, fa.y, fb.x, fb.y);
    }
}

// ---------------- launch ----------------
extern "C" void kernel_launch(void* const* d_in, const int* in_sizes, int n_in,
                              void* d_out, int out_size)
{
    const int*   seq   = (const int*)d_in[0];
    const float* embed = (const float*)d_in[1];
    const float* Wh    = (const float*)d_in[2];
    const float* Wx_w  = (const float*)d_in[3];
    const float* Wx_b  = (const float*)d_in[4];
    const float* out_w = (const float*)d_in[5];
    const float* out_b = (const float*)d_in[6];
    float* out = (float*)d_out;

    prep_kernel<<<VOCAB / 16, 256>>>(embed, Wx_w, Wx_b);          // 2000 blocks

    rnn_kernel<<<B_DIM / 32, 256>>>(seq, Wh);                     // 128 blocks

    dim3 ggrid((VOCAB + 1023) / 1024, B_DIM / 128);               // (32, 32)
    gemm_kernel<<<ggrid, 256>>>(out_w, out_b, out);
}